// round 14
// baseline (speedup 1.0000x reference)
#include <cuda_runtime.h>
#include <math.h>

#define N_NODES 50000
#define E_EDGES 800000
#define ETOT    (E_EDGES + N_NODES)   // 850000 with self loops
#define IN_DIM  128
#define HID     64
#define HEADS   4
#define HC      (HEADS * HID)         // 256
#define OUT_DIM 40
#define NEG_SLOPE 0.2f

#define SCAN_B  512
#define SCAN_NB ((N_NODES + SCAN_B - 1) / SCAN_B)   // 98

// ---------------- scratch (device globals) ---------------------------------
__device__ float g_h[(long)N_NODES * HC];
__device__ float g_accum[(long)N_NODES * HC];
__device__ float g_als[N_NODES * HEADS];
__device__ float g_ald[N_NODES * HEADS];
__device__ int   g_rp[N_NODES + 1];
__device__ int   g_cnt[N_NODES];
__device__ int   g_csr[ETOT];
__device__ int   g_bsum[SCAN_NB];
__device__ int   g_is64;

// ---------------- edge index access (dtype-robust) -------------------------
__global__ void detect_kernel(const void* ei) {
    if (threadIdx.x == 0 && blockIdx.x == 0) {
        const long long* p = (const long long*)ei;
        int ok = 1;
        for (int i = 0; i < 64; i++) {
            long long v = p[i];
            if (v < 0 || v >= N_NODES) { ok = 0; break; }
        }
        g_is64 = ok;
    }
}

__device__ __forceinline__ void edge_sd(const void* __restrict__ ei, int e,
                                        int& src, int& dst) {
    if (e >= E_EDGES) { src = dst = e - E_EDGES; return; }
    if (g_is64) {
        const long long* p = (const long long*)ei;
        src = (int)p[e];
        dst = (int)p[E_EDGES + e];
    } else {
        const int* p = (const int*)ei;
        src = p[e];
        dst = p[E_EDGES + e];
    }
}

// ---------------- CSR build ------------------------------------------------
__global__ void zero_int_kernel(int* p, int n) {
    int i = blockIdx.x * blockDim.x + threadIdx.x;
    if (i < n) p[i] = 0;
}

__global__ void zero2_kernel(float* a, float* b, int n) {
    int i = blockIdx.x * blockDim.x + threadIdx.x;
    if (i < n) { a[i] = 0.0f; b[i] = 0.0f; }
}

__global__ void count_kernel(const void* __restrict__ ei, int* __restrict__ cnt) {
    int e = blockIdx.x * blockDim.x + threadIdx.x;
    if (e >= ETOT) return;
    int src, dst;
    edge_sd(ei, e, src, dst);
    atomicAdd(&cnt[dst], 1);
}

__global__ void scan1_kernel(const int* __restrict__ cnt, int* __restrict__ rp,
                             int* __restrict__ bsum) {
    __shared__ int sm[SCAN_B];
    int i = blockIdx.x * SCAN_B + threadIdx.x;
    int v = (i < N_NODES) ? cnt[i] : 0;
    sm[threadIdx.x] = v;
    __syncthreads();
    for (int o = 1; o < SCAN_B; o <<= 1) {
        int t = (threadIdx.x >= o) ? sm[threadIdx.x - o] : 0;
        __syncthreads();
        sm[threadIdx.x] += t;
        __syncthreads();
    }
    if (i < N_NODES) rp[i] = sm[threadIdx.x] - v;
    if (threadIdx.x == SCAN_B - 1) bsum[blockIdx.x] = sm[SCAN_B - 1];
}

__global__ void scan2_kernel(int* bsum) {
    if (threadIdx.x == 0 && blockIdx.x == 0) {
        int acc = 0;
        for (int i = 0; i < SCAN_NB; i++) { int t = bsum[i]; bsum[i] = acc; acc += t; }
    }
}

__global__ void scan3_kernel(int* __restrict__ rp, const int* __restrict__ bsum) {
    int i = blockIdx.x * SCAN_B + threadIdx.x;
    if (i < N_NODES) rp[i] += bsum[blockIdx.x];
    if (i == 0) rp[N_NODES] = ETOT;
}

__global__ void fill_kernel(const void* __restrict__ ei, int* __restrict__ cnt,
                            const int* __restrict__ rp, int* __restrict__ csr) {
    int e = blockIdx.x * blockDim.x + threadIdx.x;
    if (e >= ETOT) return;
    int src, dst;
    edge_sd(ei, e, src, dst);
    int slot = rp[dst] + atomicAdd(&cnt[dst], 1);
    csr[slot] = src;
}

// ---------------- BF16 split GEMM + ldmatrix A-frags + fused logits ---------
// C = A @ B with a = ah + al (both bf16): D += ah*bh + ah*bl + al*bh.
// A fragments via ldmatrix.m8n8.x4 (1 instr = 4 regs); B scalar LDS (reused).
__device__ __forceinline__ unsigned pack_bf16x2(float lo, float hi) {
    unsigned r;
    asm("cvt.rn.bf16x2.f32 %0, %1, %2;" : "=r"(r) : "f"(hi), "f"(lo));
    return r;
}
__device__ __forceinline__ float bf16lo_f(unsigned p) { return __uint_as_float(p << 16); }
__device__ __forceinline__ float bf16hi_f(unsigned p) { return __uint_as_float(p & 0xffff0000u); }

__device__ __forceinline__ unsigned smem_u32(const void* p) {
    unsigned a;
    asm("{ .reg .u64 t; cvta.to.shared.u64 t, %1; cvt.u32.u64 %0, t; }"
        : "=r"(a) : "l"(p));
    return a;
}

#define LDMATRIX_X4(r0, r1, r2, r3, addr)                                      \
    asm volatile("ldmatrix.sync.aligned.m8n8.x4.shared.b16 {%0,%1,%2,%3}, [%4];" \
                 : "=r"(r0), "=r"(r1), "=r"(r2), "=r"(r3) : "r"(addr))

#define MMA_BF16(d, a0, a1, a2, a3, b0, b1)                                    \
    asm volatile("mma.sync.aligned.m16n8k16.row.col.f32.bf16.bf16.f32 "        \
                 "{%0,%1,%2,%3}, {%4,%5,%6,%7}, {%8,%9}, {%0,%1,%2,%3};"       \
                 : "+f"(d[0]), "+f"(d[1]), "+f"(d[2]), "+f"(d[3])              \
                 : "r"(a0), "r"(a1), "r"(a2), "r"(a3), "r"(b0), "r"(b1))

__global__ __launch_bounds__(256, 2)
void gemm_fused_kernel(const float* __restrict__ A, const float* __restrict__ B,
                       float* __restrict__ C,
                       const float* __restrict__ asrc, const float* __restrict__ adst,
                       float* __restrict__ als, float* __restrict__ ald,
                       int M, int N, int K, int H, int Chead) {
    __shared__ unsigned Ah[128][12], Al[128][12];   // [m][k/2 + pad]  k-pairs
    __shared__ unsigned Bh[8][136],  Bl[8][136];    // [k/2][n + pad]  k-pairs
    int tid  = threadIdx.x;
    int w    = tid >> 5, lane = tid & 31;
    int wm   = w >> 2,  wn   = w & 3;               // warp grid 2x4
    int grp  = lane >> 2, qk = lane & 3;
    int row0 = blockIdx.y * 128, col0 = blockIdx.x * 128;

    // ldmatrix per-lane address: matrix idx mi = lane/8 selects {row+8?, k-half}
    int mi = lane >> 3, ri = lane & 7;
    unsigned ahBase = smem_u32(&Ah[0][0]);
    unsigned alBase = smem_u32(&Al[0][0]);
    unsigned aOff = (unsigned)(((wm * 64 + (mi & 1) * 8 + ri) * 12 + (mi >> 1) * 4) * 4);

    float d[4][4][4];
    #pragma unroll
    for (int f = 0; f < 4; f++)
        #pragma unroll
        for (int g = 0; g < 4; g++)
            #pragma unroll
            for (int q = 0; q < 4; q++) d[f][g][q] = 0.0f;

    for (int bk = 0; bk < K; bk += 16) {
        // ---- A tile 128x16: 2 float4 per thread -> bf16 hi/lo k-pairs
        #pragma unroll
        for (int t = 0; t < 2; t++) {
            int i = tid + t * 256;
            int r = i >> 2, kq = i & 3;
            float4 v = make_float4(0.f, 0.f, 0.f, 0.f);
            if (row0 + r < M)
                v = *(const float4*)&A[(long)(row0 + r) * K + bk + (kq << 2)];
            unsigned h0 = pack_bf16x2(v.x, v.y);
            unsigned h1 = pack_bf16x2(v.z, v.w);
            unsigned l0 = pack_bf16x2(v.x - bf16lo_f(h0), v.y - bf16hi_f(h0));
            unsigned l1 = pack_bf16x2(v.z - bf16lo_f(h1), v.w - bf16hi_f(h1));
            *(uint2*)&Ah[r][kq << 1] = make_uint2(h0, h1);
            *(uint2*)&Al[r][kq << 1] = make_uint2(l0, l1);
        }
        // ---- B tile 16x128: thread loads rows 2kp,2kp+1 at c4 -> packed pairs
        {
            int kp = tid >> 5, c4 = (tid & 31) << 2;
            int col = col0 + c4;
            const float* r0 = &B[(long)(bk + 2 * kp) * N];
            const float* r1 = &B[(long)(bk + 2 * kp + 1) * N];
            float4 v0 = make_float4(0.f, 0.f, 0.f, 0.f);
            float4 v1 = make_float4(0.f, 0.f, 0.f, 0.f);
            if (col + 3 < N) {
                v0 = *(const float4*)&r0[col];
                v1 = *(const float4*)&r1[col];
            } else {
                if (col + 0 < N) { v0.x = r0[col + 0]; v1.x = r1[col + 0]; }
                if (col + 1 < N) { v0.y = r0[col + 1]; v1.y = r1[col + 1]; }
                if (col + 2 < N) { v0.z = r0[col + 2]; v1.z = r1[col + 2]; }
            }
            float a0[4] = {v0.x, v0.y, v0.z, v0.w};
            float a1[4] = {v1.x, v1.y, v1.z, v1.w};
            uint4 hi4, lo4;
            unsigned* hp = (unsigned*)&hi4; unsigned* lp = (unsigned*)&lo4;
            #pragma unroll
            for (int j = 0; j < 4; j++) {
                unsigned h = pack_bf16x2(a0[j], a1[j]);
                hp[j] = h;
                lp[j] = pack_bf16x2(a0[j] - bf16lo_f(h), a1[j] - bf16hi_f(h));
            }
            *(uint4*)&Bh[kp][c4] = hi4;
            *(uint4*)&Bl[kp][c4] = lo4;
        }
        __syncthreads();

        // ---- compute: one k16 step
        unsigned bh0[4], bh1[4], bl0[4], bl1[4];
        #pragma unroll
        for (int g = 0; g < 4; g++) {
            int c = wn * 32 + g * 8 + grp;
            bh0[g] = Bh[qk][c];     bh1[g] = Bh[qk + 4][c];
            bl0[g] = Bl[qk][c];     bl1[g] = Bl[qk + 4][c];
        }
        #pragma unroll
        for (int f = 0; f < 4; f++) {
            unsigned fOff = aOff + (unsigned)(f * 16 * 48);
            unsigned a0, a1, a2, a3, x0, x1, x2, x3;
            LDMATRIX_X4(a0, a1, a2, a3, ahBase + fOff);
            LDMATRIX_X4(x0, x1, x2, x3, alBase + fOff);
            #pragma unroll
            for (int g = 0; g < 4; g++) {
                MMA_BF16(d[f][g], a0, a1, a2, a3, bh0[g], bh1[g]);
                MMA_BF16(d[f][g], a0, a1, a2, a3, bl0[g], bl1[g]);
                MMA_BF16(d[f][g], x0, x1, x2, x3, bh0[g], bh1[g]);
            }
        }
        __syncthreads();
    }

    // ---- epilogue: hoist attention vectors once (f-invariant)
    float as0[4], as1[4], ad0[4], ad1[4];
    #pragma unroll
    for (int g = 0; g < 4; g++) {
        int c = col0 + wn * 32 + g * 8 + 2 * qk;
        as0[g] = (c < N)     ? asrc[c]     : 0.f;
        as1[g] = (c + 1 < N) ? asrc[c + 1] : 0.f;
        ad0[g] = (c < N)     ? adst[c]     : 0.f;
        ad1[g] = (c + 1 < N) ? adst[c + 1] : 0.f;
    }
    int hidx = (col0 + wn * 32) / Chead;
    if (hidx > H - 1) hidx = H - 1;

    #pragma unroll
    for (int f = 0; f < 4; f++) {
        int r = row0 + wm * 64 + f * 16 + grp;
        float s0 = 0.f, s1 = 0.f, dd0 = 0.f, dd1 = 0.f;
        #pragma unroll
        for (int g = 0; g < 4; g++) {
            int c = col0 + wn * 32 + g * 8 + 2 * qk;
            if (r < M) {
                if (c < N)     C[(long)r * N + c]     = d[f][g][0];
                if (c + 1 < N) C[(long)r * N + c + 1] = d[f][g][1];
            }
            if (r + 8 < M) {
                if (c < N)     C[(long)(r + 8) * N + c]     = d[f][g][2];
                if (c + 1 < N) C[(long)(r + 8) * N + c + 1] = d[f][g][3];
            }
            s0  += d[f][g][0] * as0[g] + d[f][g][1] * as1[g];
            s1  += d[f][g][2] * as0[g] + d[f][g][3] * as1[g];
            dd0 += d[f][g][0] * ad0[g] + d[f][g][1] * ad1[g];
            dd1 += d[f][g][2] * ad0[g] + d[f][g][3] * ad1[g];
        }
        #pragma unroll
        for (int off = 1; off < 4; off <<= 1) {
            s0  += __shfl_xor_sync(0xffffffffu, s0,  off);
            s1  += __shfl_xor_sync(0xffffffffu, s1,  off);
            dd0 += __shfl_xor_sync(0xffffffffu, dd0, off);
            dd1 += __shfl_xor_sync(0xffffffffu, dd1, off);
        }
        if (qk == 0) {
            if (r < M) {
                atomicAdd(&als[r * H + hidx], s0);
                atomicAdd(&ald[r * H + hidx], dd0);
            }
            if (r + 8 < M) {
                atomicAdd(&als[(r + 8) * H + hidx], s1);
                atomicAdd(&ald[(r + 8) * H + hidx], dd1);
            }
        }
    }
}

__device__ __forceinline__ float lrelu(float t) { return t > 0.0f ? t : NEG_SLOPE * t; }

// ---------------- aggregation H=4, C=64 (warp per dst, no atomics) --------
__global__ void agg4_kernel(const int* __restrict__ rp, const int* __restrict__ csr,
                            const float4* __restrict__ als4, const float4* __restrict__ ald4,
                            const float* __restrict__ hfeat, const float* __restrict__ bias,
                            float* __restrict__ out, int do_relu) {
    int w    = (blockIdx.x * blockDim.x + threadIdx.x) >> 5;
    int lane = threadIdx.x & 31;
    if (w >= N_NODES) return;
    int beg = rp[w], end = rp[w + 1];
    float4 ald = ald4[w];

    float m0 = -INFINITY, m1 = -INFINITY, m2 = -INFINITY, m3 = -INFINITY;
    for (int i = beg + lane; i < end; i += 32) {
        float4 a = als4[csr[i]];
        m0 = fmaxf(m0, lrelu(a.x + ald.x));
        m1 = fmaxf(m1, lrelu(a.y + ald.y));
        m2 = fmaxf(m2, lrelu(a.z + ald.z));
        m3 = fmaxf(m3, lrelu(a.w + ald.w));
    }
    #pragma unroll
    for (int o = 16; o > 0; o >>= 1) {
        m0 = fmaxf(m0, __shfl_xor_sync(0xffffffffu, m0, o));
        m1 = fmaxf(m1, __shfl_xor_sync(0xffffffffu, m1, o));
        m2 = fmaxf(m2, __shfl_xor_sync(0xffffffffu, m2, o));
        m3 = fmaxf(m3, __shfl_xor_sync(0xffffffffu, m3, o));
    }

    float s0 = 0.f, s1 = 0.f, s2 = 0.f, s3 = 0.f;
    for (int i = beg + lane; i < end; i += 32) {
        float4 a = als4[csr[i]];
        s0 += __expf(lrelu(a.x + ald.x) - m0);
        s1 += __expf(lrelu(a.y + ald.y) - m1);
        s2 += __expf(lrelu(a.z + ald.z) - m2);
        s3 += __expf(lrelu(a.w + ald.w) - m3);
    }
    #pragma unroll
    for (int o = 16; o > 0; o >>= 1) {
        s0 += __shfl_xor_sync(0xffffffffu, s0, o);
        s1 += __shfl_xor_sync(0xffffffffu, s1, o);
        s2 += __shfl_xor_sync(0xffffffffu, s2, o);
        s3 += __shfl_xor_sync(0xffffffffu, s3, o);
    }
    float i0 = 1.0f / s0, i1 = 1.0f / s1, i2 = 1.0f / s2, i3 = 1.0f / s3;

    float4 acc0 = make_float4(0.f, 0.f, 0.f, 0.f);
    float4 acc1 = make_float4(0.f, 0.f, 0.f, 0.f);
    const float4* h4 = (const float4*)hfeat;
    #pragma unroll 2
    for (int i = beg; i < end; i++) {
        int s = csr[i];
        float4 a = als4[s];
        float at0 = __expf(lrelu(a.x + ald.x) - m0) * i0;
        float at1 = __expf(lrelu(a.y + ald.y) - m1) * i1;
        float at2 = __expf(lrelu(a.z + ald.z) - m2) * i2;
        float at3 = __expf(lrelu(a.w + ald.w) - m3) * i3;
        float atA = (lane < 16) ? at0 : at1;
        float atB = (lane < 16) ? at2 : at3;
        float4 hv0 = h4[(long)s * 64 + lane];
        float4 hv1 = h4[(long)s * 64 + 32 + lane];
        acc0.x += hv0.x * atA; acc0.y += hv0.y * atA;
        acc0.z += hv0.z * atA; acc0.w += hv0.w * atA;
        acc1.x += hv1.x * atB; acc1.y += hv1.y * atB;
        acc1.z += hv1.z * atB; acc1.w += hv1.w * atB;
    }

    const float4* b4 = (const float4*)bias;
    float4 bv0 = b4[lane], bv1 = b4[32 + lane];
    float4 o0, o1;
    o0.x = acc0.x + bv0.x; o0.y = acc0.y + bv0.y; o0.z = acc0.z + bv0.z; o0.w = acc0.w + bv0.w;
    o1.x = acc1.x + bv1.x; o1.y = acc1.y + bv1.y; o1.z = acc1.z + bv1.z; o1.w = acc1.w + bv1.w;
    if (do_relu) {
        o0.x = fmaxf(o0.x, 0.f); o0.y = fmaxf(o0.y, 0.f); o0.z = fmaxf(o0.z, 0.f); o0.w = fmaxf(o0.w, 0.f);
        o1.x = fmaxf(o1.x, 0.f); o1.y = fmaxf(o1.y, 0.f); o1.z = fmaxf(o1.z, 0.f); o1.w = fmaxf(o1.w, 0.f);
    }
    float4* out4 = (float4*)out;
    out4[(long)w * 64 + lane]      = o0;
    out4[(long)w * 64 + 32 + lane] = o1;
}

// ---------------- aggregation H=1, C=40 ------------------------------------
__global__ void agg1_kernel(const int* __restrict__ rp, const int* __restrict__ csr,
                            const float* __restrict__ als, const float* __restrict__ ald,
                            const float* __restrict__ hfeat, const float* __restrict__ bias,
                            float* __restrict__ out) {
    int w    = (blockIdx.x * blockDim.x + threadIdx.x) >> 5;
    int lane = threadIdx.x & 31;
    if (w >= N_NODES) return;
    int beg = rp[w], end = rp[w + 1];
    float aldv = ald[w];

    float mx = -INFINITY;
    for (int i = beg + lane; i < end; i += 32)
        mx = fmaxf(mx, lrelu(als[csr[i]] + aldv));
    #pragma unroll
    for (int o = 16; o > 0; o >>= 1) mx = fmaxf(mx, __shfl_xor_sync(0xffffffffu, mx, o));

    float sm = 0.f;
    for (int i = beg + lane; i < end; i += 32)
        sm += __expf(lrelu(als[csr[i]] + aldv) - mx);
    #pragma unroll
    for (int o = 16; o > 0; o >>= 1) sm += __shfl_xor_sync(0xffffffffu, sm, o);
    float inv = 1.0f / sm;

    float4 acc = make_float4(0.f, 0.f, 0.f, 0.f);
    const float4* h4 = (const float4*)hfeat;
    #pragma unroll 2
    for (int i = beg; i < end; i++) {
        int s = csr[i];
        float at = __expf(lrelu(als[s] + aldv) - mx) * inv;
        if (lane < 10) {
            float4 hv = h4[(long)s * 10 + lane];
            acc.x += hv.x * at; acc.y += hv.y * at;
            acc.z += hv.z * at; acc.w += hv.w * at;
        }
    }
    if (lane < 10) {
        float4 bv = ((const float4*)bias)[lane];
        float4 o;
        o.x = acc.x + bv.x; o.y = acc.y + bv.y; o.z = acc.z + bv.z; o.w = acc.w + bv.w;
        ((float4*)out)[(long)w * 10 + lane] = o;
    }
}

// ---------------- log softmax over 40 dims ---------------------------------
__global__ void logsoftmax_kernel(const float* __restrict__ acc, float* __restrict__ out) {
    int n    = (blockIdx.x * blockDim.x + threadIdx.x) >> 5;
    int lane = threadIdx.x & 31;
    if (n >= N_NODES) return;
    float v0 = (lane < OUT_DIM)      ? acc[(long)n * OUT_DIM + lane]      : -INFINITY;
    float v1 = (lane + 32 < OUT_DIM) ? acc[(long)n * OUT_DIM + lane + 32] : -INFINITY;
    float mx = fmaxf(v0, v1);
    #pragma unroll
    for (int o = 16; o > 0; o >>= 1) mx = fmaxf(mx, __shfl_xor_sync(0xffffffffu, mx, o));
    float se = 0.0f;
    if (lane < OUT_DIM)      se += expf(v0 - mx);
    if (lane + 32 < OUT_DIM) se += expf(v1 - mx);
    #pragma unroll
    for (int o = 16; o > 0; o >>= 1) se += __shfl_xor_sync(0xffffffffu, se, o);
    float ls = logf(se);
    if (lane < OUT_DIM)      out[(long)n * OUT_DIM + lane]      = v0 - mx - ls;
    if (lane + 32 < OUT_DIM) out[(long)n * OUT_DIM + lane + 32] = v1 - mx - ls;
}

// ---------------- host orchestration ---------------------------------------
extern "C" void kernel_launch(void* const* d_in, const int* in_sizes, int n_in,
                              void* d_out, int out_size) {
    const float* x = 0; const void* ei = 0;
    const float *W1 = 0, *W2 = 0, *W3 = 0;
    const float* v256[6] = {0,0,0,0,0,0};
    const float* v40 [3] = {0,0,0};
    int n256 = 0, n40 = 0;
    for (int i = 0; i < n_in; i++) {
        int s = in_sizes[i];
        if      (s == N_NODES * IN_DIM)  x  = (const float*)d_in[i];
        else if (s == 2 * E_EDGES)       ei = d_in[i];
        else if (s == IN_DIM * HC)       W1 = (const float*)d_in[i];
        else if (s == HC * HC)           W2 = (const float*)d_in[i];
        else if (s == HC * OUT_DIM)      W3 = (const float*)d_in[i];
        else if (s == HC      && n256 < 6) v256[n256++] = (const float*)d_in[i];
        else if (s == OUT_DIM && n40  < 3) v40 [n40++]  = (const float*)d_in[i];
    }
    const float *as1 = v256[0], *ad1 = v256[1], *b1 = v256[2];
    const float *as2 = v256[3], *ad2 = v256[4], *b2 = v256[5];
    const float *as3 = v40[0],  *ad3 = v40[1],  *b3 = v40[2];
    float* out = (float*)d_out;

    float *hbuf, *accum, *als, *ald; int *rp, *cnt, *csr, *bsum;
    cudaGetSymbolAddress((void**)&hbuf,  g_h);
    cudaGetSymbolAddress((void**)&accum, g_accum);
    cudaGetSymbolAddress((void**)&als,   g_als);
    cudaGetSymbolAddress((void**)&ald,   g_ald);
    cudaGetSymbolAddress((void**)&rp,    g_rp);
    cudaGetSymbolAddress((void**)&cnt,   g_cnt);
    cudaGetSymbolAddress((void**)&csr,   g_csr);
    cudaGetSymbolAddress((void**)&bsum,  g_bsum);

    // side stream + events for CSR-build overlap (fork/join; graph-capturable)
    cudaStream_t s0 = 0, s1;
    cudaStreamCreateWithFlags(&s1, cudaStreamNonBlocking);
    cudaEvent_t evF, evJ;
    cudaEventCreateWithFlags(&evF, cudaEventDisableTiming);
    cudaEventCreateWithFlags(&evJ, cudaEventDisableTiming);

    int aggBlocks = (N_NODES * 32 + 255) / 256;
    int mBlocks   = (N_NODES + 127) / 128;
    int nmh = N_NODES * HEADS;

    // fork: CSR build on s1; zero+GEMM(layer1, fused logits) on s0
    cudaEventRecord(evF, s0);
    cudaStreamWaitEvent(s1, evF, 0);
    detect_kernel<<<1, 32, 0, s1>>>(ei);                                    // 1
    zero2_kernel<<<(nmh + 255) / 256, 256, 0, s0>>>(als, ald, nmh);         // 2
    zero_int_kernel<<<(N_NODES + 255) / 256, 256, 0, s1>>>(cnt, N_NODES);   // 3
    {
        dim3 gg(HC / 128, mBlocks);
        gemm_fused_kernel<<<gg, 256, 0, s0>>>(x, W1, hbuf, as1, ad1, als, ald,
                                              N_NODES, HC, IN_DIM, HEADS, HID); // 4
    }
    count_kernel<<<(ETOT + 255) / 256, 256, 0, s1>>>(ei, cnt);
    scan1_kernel<<<SCAN_NB, SCAN_B, 0, s1>>>(cnt, rp, bsum);
    scan2_kernel<<<1, 32, 0, s1>>>(bsum);
    scan3_kernel<<<SCAN_NB, SCAN_B, 0, s1>>>(rp, bsum);
    zero_int_kernel<<<(N_NODES + 255) / 256, 256, 0, s1>>>(cnt, N_NODES);
    fill_kernel<<<(ETOT + 255) / 256, 256, 0, s1>>>(ei, cnt, rp, csr);
    cudaEventRecord(evJ, s1);

    cudaStreamWaitEvent(s0, evJ, 0);   // join: agg needs CSR
    agg4_kernel<<<aggBlocks, 256, 0, s0>>>(rp, csr, (const float4*)als, (const float4*)ald,
                                           hbuf, b1, accum, 1);

    // ---- layer 2: accum[N,256] -> accum[N,256]
    zero2_kernel<<<(nmh + 255) / 256, 256, 0, s0>>>(als, ald, nmh);
    {
        dim3 gg(HC / 128, mBlocks);
        gemm_fused_kernel<<<gg, 256, 0, s0>>>(accum, W2, hbuf, as2, ad2, als, ald,
                                              N_NODES, HC, HC, HEADS, HID);
        agg4_kernel<<<aggBlocks, 256, 0, s0>>>(rp, csr, (const float4*)als, (const float4*)ald,
                                               hbuf, b2, accum, 1);
    }
    // ---- layer 3: accum[N,256] -> accum[N,40] -> log_softmax -> out
    zero2_kernel<<<(N_NODES + 255) / 256, 256, 0, s0>>>(als, ald, N_NODES);
    {
        dim3 gg(1, mBlocks);
        gemm_fused_kernel<<<gg, 256, 0, s0>>>(accum, W3, hbuf, as3, ad3, als, ald,
                                              N_NODES, OUT_DIM, HC, 1, OUT_DIM);
        agg1_kernel<<<aggBlocks, 256, 0, s0>>>(rp, csr, als, ald, hbuf, b3, accum);
        logsoftmax_kernel<<<(N_NODES * 32 + 255) / 256, 256, 0, s0>>>(accum, out);
    }

    cudaEventDestroy(evF);
    cudaEventDestroy(evJ);
    cudaStreamDestroy(s1);
    (void)n_in; (void)out_size;
}

// round 15
// speedup vs baseline: 1.0440x; 1.0440x over previous
#include <cuda_runtime.h>
#include <math.h>

#define N_NODES 50000
#define E_EDGES 800000
#define ETOT    (E_EDGES + N_NODES)   // 850000 with self loops
#define IN_DIM  128
#define HID     64
#define HEADS   4
#define HC      (HEADS * HID)         // 256
#define OUT_DIM 40
#define NEG_SLOPE 0.2f

#define SCAN_B  512
#define SCAN_NB ((N_NODES + SCAN_B - 1) / SCAN_B)   // 98

// ---------------- scratch (device globals) ---------------------------------
__device__ float g_h[(long)N_NODES * HC];
__device__ float g_accum[(long)N_NODES * HC];
__device__ float g_als[N_NODES * HEADS];
__device__ float g_ald[N_NODES * HEADS];
__device__ int   g_rp[N_NODES + 1];
__device__ int   g_cnt[N_NODES];
__device__ int   g_csr[ETOT];
__device__ int   g_bsum[SCAN_NB];
__device__ int   g_is64;

// ---------------- edge index access (dtype-robust) -------------------------
__global__ void detect_kernel(const void* ei) {
    if (threadIdx.x == 0 && blockIdx.x == 0) {
        const long long* p = (const long long*)ei;
        int ok = 1;
        for (int i = 0; i < 64; i++) {
            long long v = p[i];
            if (v < 0 || v >= N_NODES) { ok = 0; break; }
        }
        g_is64 = ok;
    }
}

__device__ __forceinline__ void edge_sd(const void* __restrict__ ei, int e,
                                        int& src, int& dst) {
    if (e >= E_EDGES) { src = dst = e - E_EDGES; return; }
    if (g_is64) {
        const long long* p = (const long long*)ei;
        src = (int)p[e];
        dst = (int)p[E_EDGES + e];
    } else {
        const int* p = (const int*)ei;
        src = p[e];
        dst = p[E_EDGES + e];
    }
}

// ---------------- CSR build ------------------------------------------------
__global__ void zero_int_kernel(int* p, int n) {
    int i = blockIdx.x * blockDim.x + threadIdx.x;
    if (i < n) p[i] = 0;
}

__global__ void zero2_kernel(float* a, float* b, int n) {
    int i = blockIdx.x * blockDim.x + threadIdx.x;
    if (i < n) { a[i] = 0.0f; b[i] = 0.0f; }
}

__global__ void count_kernel(const void* __restrict__ ei, int* __restrict__ cnt) {
    int e = blockIdx.x * blockDim.x + threadIdx.x;
    if (e >= ETOT) return;
    int src, dst;
    edge_sd(ei, e, src, dst);
    atomicAdd(&cnt[dst], 1);
}

__global__ void scan1_kernel(const int* __restrict__ cnt, int* __restrict__ rp,
                             int* __restrict__ bsum) {
    __shared__ int sm[SCAN_B];
    int i = blockIdx.x * SCAN_B + threadIdx.x;
    int v = (i < N_NODES) ? cnt[i] : 0;
    sm[threadIdx.x] = v;
    __syncthreads();
    for (int o = 1; o < SCAN_B; o <<= 1) {
        int t = (threadIdx.x >= o) ? sm[threadIdx.x - o] : 0;
        __syncthreads();
        sm[threadIdx.x] += t;
        __syncthreads();
    }
    if (i < N_NODES) rp[i] = sm[threadIdx.x] - v;
    if (threadIdx.x == SCAN_B - 1) bsum[blockIdx.x] = sm[SCAN_B - 1];
}

__global__ void scan2_kernel(int* bsum) {
    if (threadIdx.x == 0 && blockIdx.x == 0) {
        int acc = 0;
        for (int i = 0; i < SCAN_NB; i++) { int t = bsum[i]; bsum[i] = acc; acc += t; }
    }
}

__global__ void scan3_kernel(int* __restrict__ rp, const int* __restrict__ bsum) {
    int i = blockIdx.x * SCAN_B + threadIdx.x;
    if (i < N_NODES) rp[i] += bsum[blockIdx.x];
    if (i == 0) rp[N_NODES] = ETOT;
}

__global__ void fill_kernel(const void* __restrict__ ei, int* __restrict__ cnt,
                            const int* __restrict__ rp, int* __restrict__ csr) {
    int e = blockIdx.x * blockDim.x + threadIdx.x;
    if (e >= ETOT) return;
    int src, dst;
    edge_sd(ei, e, src, dst);
    int slot = rp[dst] + atomicAdd(&cnt[dst], 1);
    csr[slot] = src;
}

// ---------------- BF16 split GEMM (R12-proven) + fused logits ---------------
// C = A @ B with a = ah + al (both bf16): D += ah*bh + ah*bl + al*bh.
// mma.m16n8k16.bf16: k-pairs packed in b32 regs (low half = even k).
// BM=128, BN=128, BK=16, 256 threads, warp tile 64x32 (2x4 warps), 2 CTAs/SM.
__device__ __forceinline__ unsigned pack_bf16x2(float lo, float hi) {
    unsigned r;
    asm("cvt.rn.bf16x2.f32 %0, %1, %2;" : "=r"(r) : "f"(hi), "f"(lo));
    return r;
}
__device__ __forceinline__ float bf16lo_f(unsigned p) { return __uint_as_float(p << 16); }
__device__ __forceinline__ float bf16hi_f(unsigned p) { return __uint_as_float(p & 0xffff0000u); }

#define MMA_BF16(d, a0, a1, a2, a3, b0, b1)                                    \
    asm volatile("mma.sync.aligned.m16n8k16.row.col.f32.bf16.bf16.f32 "        \
                 "{%0,%1,%2,%3}, {%4,%5,%6,%7}, {%8,%9}, {%0,%1,%2,%3};"       \
                 : "+f"(d[0]), "+f"(d[1]), "+f"(d[2]), "+f"(d[3])              \
                 : "r"(a0), "r"(a1), "r"(a2), "r"(a3), "r"(b0), "r"(b1))

__global__ __launch_bounds__(256, 2)
void gemm_fused_kernel(const float* __restrict__ A, const float* __restrict__ B,
                       float* __restrict__ C,
                       const float* __restrict__ asrc, const float* __restrict__ adst,
                       float* __restrict__ als, float* __restrict__ ald,
                       int M, int N, int K, int H, int Chead) {
    __shared__ unsigned Ah[128][12], Al[128][12];   // [m][k/2 + pad]  k-pairs
    __shared__ unsigned Bh[8][136],  Bl[8][136];    // [k/2][n + pad]  k-pairs
    int tid  = threadIdx.x;
    int w    = tid >> 5, lane = tid & 31;
    int wm   = w >> 2,  wn   = w & 3;               // warp grid 2x4
    int grp  = lane >> 2, qk = lane & 3;
    int row0 = blockIdx.y * 128, col0 = blockIdx.x * 128;

    float d[4][4][4];
    #pragma unroll
    for (int f = 0; f < 4; f++)
        #pragma unroll
        for (int g = 0; g < 4; g++)
            #pragma unroll
            for (int q = 0; q < 4; q++) d[f][g][q] = 0.0f;

    for (int bk = 0; bk < K; bk += 16) {
        // ---- A tile 128x16: 2 float4 per thread -> bf16 hi/lo k-pairs
        #pragma unroll
        for (int t = 0; t < 2; t++) {
            int i = tid + t * 256;
            int r = i >> 2, kq = i & 3;
            float4 v = make_float4(0.f, 0.f, 0.f, 0.f);
            if (row0 + r < M)
                v = *(const float4*)&A[(long)(row0 + r) * K + bk + (kq << 2)];
            unsigned h0 = pack_bf16x2(v.x, v.y);
            unsigned h1 = pack_bf16x2(v.z, v.w);
            unsigned l0 = pack_bf16x2(v.x - bf16lo_f(h0), v.y - bf16hi_f(h0));
            unsigned l1 = pack_bf16x2(v.z - bf16lo_f(h1), v.w - bf16hi_f(h1));
            *(uint2*)&Ah[r][kq << 1] = make_uint2(h0, h1);
            *(uint2*)&Al[r][kq << 1] = make_uint2(l0, l1);
        }
        // ---- B tile 16x128: thread loads rows 2kp,2kp+1 at c4 -> packed pairs
        {
            int kp = tid >> 5, c4 = (tid & 31) << 2;
            int col = col0 + c4;
            const float* r0 = &B[(long)(bk + 2 * kp) * N];
            const float* r1 = &B[(long)(bk + 2 * kp + 1) * N];
            float4 v0 = make_float4(0.f, 0.f, 0.f, 0.f);
            float4 v1 = make_float4(0.f, 0.f, 0.f, 0.f);
            if (col + 3 < N) {
                v0 = *(const float4*)&r0[col];
                v1 = *(const float4*)&r1[col];
            } else {
                if (col + 0 < N) { v0.x = r0[col + 0]; v1.x = r1[col + 0]; }
                if (col + 1 < N) { v0.y = r0[col + 1]; v1.y = r1[col + 1]; }
                if (col + 2 < N) { v0.z = r0[col + 2]; v1.z = r1[col + 2]; }
            }
            float a0[4] = {v0.x, v0.y, v0.z, v0.w};
            float a1[4] = {v1.x, v1.y, v1.z, v1.w};
            uint4 hi4, lo4;
            unsigned* hp = (unsigned*)&hi4; unsigned* lp = (unsigned*)&lo4;
            #pragma unroll
            for (int j = 0; j < 4; j++) {
                unsigned h = pack_bf16x2(a0[j], a1[j]);
                hp[j] = h;
                lp[j] = pack_bf16x2(a0[j] - bf16lo_f(h), a1[j] - bf16hi_f(h));
            }
            *(uint4*)&Bh[kp][c4] = hi4;
            *(uint4*)&Bl[kp][c4] = lo4;
        }
        __syncthreads();

        // ---- compute: one k16 step
        unsigned bh0[4], bh1[4], bl0[4], bl1[4];
        #pragma unroll
        for (int g = 0; g < 4; g++) {
            int c = wn * 32 + g * 8 + grp;
            bh0[g] = Bh[qk][c];     bh1[g] = Bh[qk + 4][c];
            bl0[g] = Bl[qk][c];     bl1[g] = Bl[qk + 4][c];
        }
        #pragma unroll
        for (int f = 0; f < 4; f++) {
            int r = wm * 64 + f * 16 + grp;
            unsigned a0 = Ah[r][qk],     a1 = Ah[r + 8][qk];
            unsigned a2 = Ah[r][qk + 4], a3 = Ah[r + 8][qk + 4];
            unsigned x0 = Al[r][qk],     x1 = Al[r + 8][qk];
            unsigned x2 = Al[r][qk + 4], x3 = Al[r + 8][qk + 4];
            #pragma unroll
            for (int g = 0; g < 4; g++) {
                MMA_BF16(d[f][g], a0, a1, a2, a3, bh0[g], bh1[g]);
                MMA_BF16(d[f][g], a0, a1, a2, a3, bl0[g], bl1[g]);
                MMA_BF16(d[f][g], x0, x1, x2, x3, bh0[g], bh1[g]);
            }
        }
        __syncthreads();
    }

    // ---- epilogue: hoist attention vectors once (f-invariant)
    float as0[4], as1[4], ad0[4], ad1[4];
    #pragma unroll
    for (int g = 0; g < 4; g++) {
        int c = col0 + wn * 32 + g * 8 + 2 * qk;
        as0[g] = (c < N)     ? asrc[c]     : 0.f;
        as1[g] = (c + 1 < N) ? asrc[c + 1] : 0.f;
        ad0[g] = (c < N)     ? adst[c]     : 0.f;
        ad1[g] = (c + 1 < N) ? adst[c + 1] : 0.f;
    }
    int hidx = (col0 + wn * 32) / Chead;
    if (hidx > H - 1) hidx = H - 1;

    #pragma unroll
    for (int f = 0; f < 4; f++) {
        int r = row0 + wm * 64 + f * 16 + grp;
        float s0 = 0.f, s1 = 0.f, dd0 = 0.f, dd1 = 0.f;
        #pragma unroll
        for (int g = 0; g < 4; g++) {
            int c = col0 + wn * 32 + g * 8 + 2 * qk;
            if (r < M) {
                if (c < N)     C[(long)r * N + c]     = d[f][g][0];
                if (c + 1 < N) C[(long)r * N + c + 1] = d[f][g][1];
            }
            if (r + 8 < M) {
                if (c < N)     C[(long)(r + 8) * N + c]     = d[f][g][2];
                if (c + 1 < N) C[(long)(r + 8) * N + c + 1] = d[f][g][3];
            }
            s0  += d[f][g][0] * as0[g] + d[f][g][1] * as1[g];
            s1  += d[f][g][2] * as0[g] + d[f][g][3] * as1[g];
            dd0 += d[f][g][0] * ad0[g] + d[f][g][1] * ad1[g];
            dd1 += d[f][g][2] * ad0[g] + d[f][g][3] * ad1[g];
        }
        #pragma unroll
        for (int off = 1; off < 4; off <<= 1) {
            s0  += __shfl_xor_sync(0xffffffffu, s0,  off);
            s1  += __shfl_xor_sync(0xffffffffu, s1,  off);
            dd0 += __shfl_xor_sync(0xffffffffu, dd0, off);
            dd1 += __shfl_xor_sync(0xffffffffu, dd1, off);
        }
        if (qk == 0) {
            if (r < M) {
                atomicAdd(&als[r * H + hidx], s0);
                atomicAdd(&ald[r * H + hidx], dd0);
            }
            if (r + 8 < M) {
                atomicAdd(&als[(r + 8) * H + hidx], s1);
                atomicAdd(&ald[(r + 8) * H + hidx], dd1);
            }
        }
    }
}

__device__ __forceinline__ float lrelu(float t) { return t > 0.0f ? t : NEG_SLOPE * t; }

// ---------------- aggregation H=4, C=64 (warp per dst, no atomics) --------
__global__ void agg4_kernel(const int* __restrict__ rp, const int* __restrict__ csr,
                            const float4* __restrict__ als4, const float4* __restrict__ ald4,
                            const float* __restrict__ hfeat, const float* __restrict__ bias,
                            float* __restrict__ out, int do_relu) {
    int w    = (blockIdx.x * blockDim.x + threadIdx.x) >> 5;
    int lane = threadIdx.x & 31;
    if (w >= N_NODES) return;
    int beg = rp[w], end = rp[w + 1];
    float4 ald = ald4[w];

    float m0 = -INFINITY, m1 = -INFINITY, m2 = -INFINITY, m3 = -INFINITY;
    for (int i = beg + lane; i < end; i += 32) {
        float4 a = als4[csr[i]];
        m0 = fmaxf(m0, lrelu(a.x + ald.x));
        m1 = fmaxf(m1, lrelu(a.y + ald.y));
        m2 = fmaxf(m2, lrelu(a.z + ald.z));
        m3 = fmaxf(m3, lrelu(a.w + ald.w));
    }
    #pragma unroll
    for (int o = 16; o > 0; o >>= 1) {
        m0 = fmaxf(m0, __shfl_xor_sync(0xffffffffu, m0, o));
        m1 = fmaxf(m1, __shfl_xor_sync(0xffffffffu, m1, o));
        m2 = fmaxf(m2, __shfl_xor_sync(0xffffffffu, m2, o));
        m3 = fmaxf(m3, __shfl_xor_sync(0xffffffffu, m3, o));
    }

    float s0 = 0.f, s1 = 0.f, s2 = 0.f, s3 = 0.f;
    for (int i = beg + lane; i < end; i += 32) {
        float4 a = als4[csr[i]];
        s0 += __expf(lrelu(a.x + ald.x) - m0);
        s1 += __expf(lrelu(a.y + ald.y) - m1);
        s2 += __expf(lrelu(a.z + ald.z) - m2);
        s3 += __expf(lrelu(a.w + ald.w) - m3);
    }
    #pragma unroll
    for (int o = 16; o > 0; o >>= 1) {
        s0 += __shfl_xor_sync(0xffffffffu, s0, o);
        s1 += __shfl_xor_sync(0xffffffffu, s1, o);
        s2 += __shfl_xor_sync(0xffffffffu, s2, o);
        s3 += __shfl_xor_sync(0xffffffffu, s3, o);
    }
    float i0 = 1.0f / s0, i1 = 1.0f / s1, i2 = 1.0f / s2, i3 = 1.0f / s3;

    // per-lane head selection: lane handles chunks (lane) and (lane+32).
    // chunk f: head = f >> 4 -> head A = (lane<16)?0:1, head B = (lane<16)?2:3
    bool loA = (lane < 16);
    float aldA = loA ? ald.x : ald.y,  mA = loA ? m0 : m1,  iA = loA ? i0 : i1;
    float aldB = loA ? ald.z : ald.w,  mB = loA ? m2 : m3,  iB = loA ? i2 : i3;

    float4 acc0 = make_float4(0.f, 0.f, 0.f, 0.f);
    float4 acc1 = make_float4(0.f, 0.f, 0.f, 0.f);
    const float4* h4 = (const float4*)hfeat;
    #pragma unroll 4
    for (int i = beg; i < end; i++) {
        int s = csr[i];
        float4 a = als4[s];
        float aA = loA ? a.x : a.y;
        float aB = loA ? a.z : a.w;
        float atA = __expf(lrelu(aA + aldA) - mA) * iA;
        float atB = __expf(lrelu(aB + aldB) - mB) * iB;
        float4 hv0 = h4[(long)s * 64 + lane];
        float4 hv1 = h4[(long)s * 64 + 32 + lane];
        acc0.x += hv0.x * atA; acc0.y += hv0.y * atA;
        acc0.z += hv0.z * atA; acc0.w += hv0.w * atA;
        acc1.x += hv1.x * atB; acc1.y += hv1.y * atB;
        acc1.z += hv1.z * atB; acc1.w += hv1.w * atB;
    }

    const float4* b4 = (const float4*)bias;
    float4 bv0 = b4[lane], bv1 = b4[32 + lane];
    float4 o0, o1;
    o0.x = acc0.x + bv0.x; o0.y = acc0.y + bv0.y; o0.z = acc0.z + bv0.z; o0.w = acc0.w + bv0.w;
    o1.x = acc1.x + bv1.x; o1.y = acc1.y + bv1.y; o1.z = acc1.z + bv1.z; o1.w = acc1.w + bv1.w;
    if (do_relu) {
        o0.x = fmaxf(o0.x, 0.f); o0.y = fmaxf(o0.y, 0.f); o0.z = fmaxf(o0.z, 0.f); o0.w = fmaxf(o0.w, 0.f);
        o1.x = fmaxf(o1.x, 0.f); o1.y = fmaxf(o1.y, 0.f); o1.z = fmaxf(o1.z, 0.f); o1.w = fmaxf(o1.w, 0.f);
    }
    float4* out4 = (float4*)out;
    out4[(long)w * 64 + lane]      = o0;
    out4[(long)w * 64 + 32 + lane] = o1;
}

// ---------------- aggregation H=1, C=40 ------------------------------------
__global__ void agg1_kernel(const int* __restrict__ rp, const int* __restrict__ csr,
                            const float* __restrict__ als, const float* __restrict__ ald,
                            const float* __restrict__ hfeat, const float* __restrict__ bias,
                            float* __restrict__ out) {
    int w    = (blockIdx.x * blockDim.x + threadIdx.x) >> 5;
    int lane = threadIdx.x & 31;
    if (w >= N_NODES) return;
    int beg = rp[w], end = rp[w + 1];
    float aldv = ald[w];

    float mx = -INFINITY;
    for (int i = beg + lane; i < end; i += 32)
        mx = fmaxf(mx, lrelu(als[csr[i]] + aldv));
    #pragma unroll
    for (int o = 16; o > 0; o >>= 1) mx = fmaxf(mx, __shfl_xor_sync(0xffffffffu, mx, o));

    float sm = 0.f;
    for (int i = beg + lane; i < end; i += 32)
        sm += __expf(lrelu(als[csr[i]] + aldv) - mx);
    #pragma unroll
    for (int o = 16; o > 0; o >>= 1) sm += __shfl_xor_sync(0xffffffffu, sm, o);
    float inv = 1.0f / sm;

    float4 acc = make_float4(0.f, 0.f, 0.f, 0.f);
    const float4* h4 = (const float4*)hfeat;
    #pragma unroll 2
    for (int i = beg; i < end; i++) {
        int s = csr[i];
        float at = __expf(lrelu(als[s] + aldv) - mx) * inv;
        if (lane < 10) {
            float4 hv = h4[(long)s * 10 + lane];
            acc.x += hv.x * at; acc.y += hv.y * at;
            acc.z += hv.z * at; acc.w += hv.w * at;
        }
    }
    if (lane < 10) {
        float4 bv = ((const float4*)bias)[lane];
        float4 o;
        o.x = acc.x + bv.x; o.y = acc.y + bv.y; o.z = acc.z + bv.z; o.w = acc.w + bv.w;
        ((float4*)out)[(long)w * 10 + lane] = o;
    }
}

// ---------------- log softmax over 40 dims ---------------------------------
__global__ void logsoftmax_kernel(const float* __restrict__ acc, float* __restrict__ out) {
    int n    = (blockIdx.x * blockDim.x + threadIdx.x) >> 5;
    int lane = threadIdx.x & 31;
    if (n >= N_NODES) return;
    float v0 = (lane < OUT_DIM)      ? acc[(long)n * OUT_DIM + lane]      : -INFINITY;
    float v1 = (lane + 32 < OUT_DIM) ? acc[(long)n * OUT_DIM + lane + 32] : -INFINITY;
    float mx = fmaxf(v0, v1);
    #pragma unroll
    for (int o = 16; o > 0; o >>= 1) mx = fmaxf(mx, __shfl_xor_sync(0xffffffffu, mx, o));
    float se = 0.0f;
    if (lane < OUT_DIM)      se += expf(v0 - mx);
    if (lane + 32 < OUT_DIM) se += expf(v1 - mx);
    #pragma unroll
    for (int o = 16; o > 0; o >>= 1) se += __shfl_xor_sync(0xffffffffu, se, o);
    float ls = logf(se);
    if (lane < OUT_DIM)      out[(long)n * OUT_DIM + lane]      = v0 - mx - ls;
    if (lane + 32 < OUT_DIM) out[(long)n * OUT_DIM + lane + 32] = v1 - mx - ls;
}

// ---------------- host orchestration ---------------------------------------
extern "C" void kernel_launch(void* const* d_in, const int* in_sizes, int n_in,
                              void* d_out, int out_size) {
    const float* x = 0; const void* ei = 0;
    const float *W1 = 0, *W2 = 0, *W3 = 0;
    const float* v256[6] = {0,0,0,0,0,0};
    const float* v40 [3] = {0,0,0};
    int n256 = 0, n40 = 0;
    for (int i = 0; i < n_in; i++) {
        int s = in_sizes[i];
        if      (s == N_NODES * IN_DIM)  x  = (const float*)d_in[i];
        else if (s == 2 * E_EDGES)       ei = d_in[i];
        else if (s == IN_DIM * HC)       W1 = (const float*)d_in[i];
        else if (s == HC * HC)           W2 = (const float*)d_in[i];
        else if (s == HC * OUT_DIM)      W3 = (const float*)d_in[i];
        else if (s == HC      && n256 < 6) v256[n256++] = (const float*)d_in[i];
        else if (s == OUT_DIM && n40  < 3) v40 [n40++]  = (const float*)d_in[i];
    }
    const float *as1 = v256[0], *ad1 = v256[1], *b1 = v256[2];
    const float *as2 = v256[3], *ad2 = v256[4], *b2 = v256[5];
    const float *as3 = v40[0],  *ad3 = v40[1],  *b3 = v40[2];
    float* out = (float*)d_out;

    float *hbuf, *accum, *als, *ald; int *rp, *cnt, *csr, *bsum;
    cudaGetSymbolAddress((void**)&hbuf,  g_h);
    cudaGetSymbolAddress((void**)&accum, g_accum);
    cudaGetSymbolAddress((void**)&als,   g_als);
    cudaGetSymbolAddress((void**)&ald,   g_ald);
    cudaGetSymbolAddress((void**)&rp,    g_rp);
    cudaGetSymbolAddress((void**)&cnt,   g_cnt);
    cudaGetSymbolAddress((void**)&csr,   g_csr);
    cudaGetSymbolAddress((void**)&bsum,  g_bsum);

    // side stream + events for CSR-build overlap (fork/join; graph-capturable)
    cudaStream_t s0 = 0, s1;
    cudaStreamCreateWithFlags(&s1, cudaStreamNonBlocking);
    cudaEvent_t evF, evJ;
    cudaEventCreateWithFlags(&evF, cudaEventDisableTiming);
    cudaEventCreateWithFlags(&evJ, cudaEventDisableTiming);

    int aggBlocks = (N_NODES * 32 + 255) / 256;
    int mBlocks   = (N_NODES + 127) / 128;
    int nmh = N_NODES * HEADS;

    // fork: CSR build on s1; zero+GEMM(layer1, fused logits) on s0
    cudaEventRecord(evF, s0);
    cudaStreamWaitEvent(s1, evF, 0);
    detect_kernel<<<1, 32, 0, s1>>>(ei);
    zero2_kernel<<<(nmh + 255) / 256, 256, 0, s0>>>(als, ald, nmh);
    zero_int_kernel<<<(N_NODES + 255) / 256, 256, 0, s1>>>(cnt, N_NODES);
    {
        dim3 gg(HC / 128, mBlocks);
        gemm_fused_kernel<<<gg, 256, 0, s0>>>(x, W1, hbuf, as1, ad1, als, ald,
                                              N_NODES, HC, IN_DIM, HEADS, HID);
    }
    count_kernel<<<(ETOT + 255) / 256, 256, 0, s1>>>(ei, cnt);
    scan1_kernel<<<SCAN_NB, SCAN_B, 0, s1>>>(cnt, rp, bsum);
    scan2_kernel<<<1, 32, 0, s1>>>(bsum);
    scan3_kernel<<<SCAN_NB, SCAN_B, 0, s1>>>(rp, bsum);
    zero_int_kernel<<<(N_NODES + 255) / 256, 256, 0, s1>>>(cnt, N_NODES);
    fill_kernel<<<(ETOT + 255) / 256, 256, 0, s1>>>(ei, cnt, rp, csr);
    cudaEventRecord(evJ, s1);

    cudaStreamWaitEvent(s0, evJ, 0);   // join: agg needs CSR
    agg4_kernel<<<aggBlocks, 256, 0, s0>>>(rp, csr, (const float4*)als, (const float4*)ald,
                                           hbuf, b1, accum, 1);

    // ---- layer 2: accum[N,256] -> accum[N,256]
    zero2_kernel<<<(nmh + 255) / 256, 256, 0, s0>>>(als, ald, nmh);
    {
        dim3 gg(HC / 128, mBlocks);
        gemm_fused_kernel<<<gg, 256, 0, s0>>>(accum, W2, hbuf, as2, ad2, als, ald,
                                              N_NODES, HC, HC, HEADS, HID);
        agg4_kernel<<<aggBlocks, 256, 0, s0>>>(rp, csr, (const float4*)als, (const float4*)ald,
                                               hbuf, b2, accum, 1);
    }
    // ---- layer 3: accum[N,256] -> accum[N,40] -> log_softmax -> out
    zero2_kernel<<<(N_NODES + 255) / 256, 256, 0, s0>>>(als, ald, N_NODES);
    {
        dim3 gg(1, mBlocks);
        gemm_fused_kernel<<<gg, 256, 0, s0>>>(accum, W3, hbuf, as3, ad3, als, ald,
                                              N_NODES, OUT_DIM, HC, 1, OUT_DIM);
        agg1_kernel<<<aggBlocks, 256, 0, s0>>>(rp, csr, als, ald, hbuf, b3, accum);
        logsoftmax_kernel<<<(N_NODES * 32 + 255) / 256, 256, 0, s0>>>(accum, out);
    }

    cudaEventDestroy(evF);
    cudaEventDestroy(evJ);
    cudaStreamDestroy(s1);
    (void)n_in; (void)out_size;
}